// round 16
// baseline (speedup 1.0000x reference)
#include <cuda_runtime.h>
#include <cuda_fp16.h>
#include <cstdint>

// ---------------------------------------------------------------------------
// Swin WindowAttention, persistent FP16 mma.sync kernel (m16n8k16), round 16.
// Byte-bound optimization: G1 on 8 warps with 32x96 tiles (0.67 LDS/mma),
// G4 on 8 warps with 32x32 tiles while warps 8-15 stage next x. Scale folded
// into prepacked qkv weights/bias. Weights resident in smem. 512 threads.
// ---------------------------------------------------------------------------

namespace {
constexpr int NTOK  = 49;
constexpr int CDIM  = 128;
constexpr int NHEAD = 4;
constexpr int TC3   = 384;
constexpr int MAXW  = 64;
constexpr int S     = 144;   // fp16-unit stride (288 B), conflict-free
constexpr int SVT   = 80;    // VT stride

constexpr int OFF_WQ = 0;                    // [384][144] qkv_w resident
constexpr int OFF_WP = OFF_WQ + 384 * S;     // [128][144] proj_w resident
constexpr int OFF_X0 = OFF_WP + 128 * S;     // [64][144] ping buffer (x/ao or Q)
constexpr int OFF_X1 = OFF_X0 + 64 * S;      // [64][144] pong buffer
constexpr int OFF_K  = OFF_X1 + 64 * S;      // [64][144] K
constexpr int OFF_VT = OFF_K  + 64 * S;      // [128][80] V^T
constexpr int OFF_BQ = OFF_VT + 128 * SVT;   // 384 fp32 qkv_b + 128 fp32 proj_b
constexpr int SMEMH  = OFF_BQ + 1024;        // 112640 halfs = 225280 B
}

__device__ __half g_wqkv_h[TC3 * CDIM];            // [n=384][pk16(k=128)], Q pre-scaled
__device__ __half g_wproj_h[CDIM * CDIM];          // [n=128][pk16(k=128)]
__device__ float  g_rm[MAXW * NHEAD * 64 * 64];    // rpb+mask, padded -1e30

__device__ __forceinline__ int pk16(int k) {
    return (k & ~15) | (((k >> 1) & 3) << 2) | ((k & 8) >> 2) | (k & 1);
}

__device__ __forceinline__ uint32_t h2u(float a, float b) {
    __half2 h = __floats2half2_rn(a, b);
    return *reinterpret_cast<uint32_t*>(&h);
}

__device__ __forceinline__ void mma16(float* c, uint2 alo, uint2 ahi, uint2 b) {
    asm volatile(
        "mma.sync.aligned.m16n8k16.row.col.f32.f16.f16.f32 "
        "{%0,%1,%2,%3}, {%4,%5,%6,%7}, {%8,%9}, {%0,%1,%2,%3};"
        : "+f"(c[0]), "+f"(c[1]), "+f"(c[2]), "+f"(c[3])
        : "r"(alo.x), "r"(ahi.x), "r"(alo.y), "r"(ahi.y), "r"(b.x), "r"(b.y));
}

__device__ __forceinline__ uint32_t ex2h2(float a, float b) {
    __half2 h = __floats2half2_rn(a, b);
    uint32_t r;
    asm("ex2.approx.f16x2 %0, %1;" : "=r"(r) : "r"(*reinterpret_cast<uint32_t*>(&h)));
    return r;
}

// ---------------- prepack kernels ------------------------------------------
__global__ void prepack_w(const float* __restrict__ qkv_w,
                          const float* __restrict__ proj_w) {
    const float scale = 0.17677669529663687f;   // 32^-0.5, folded into Q cols
    int t = blockIdx.x * blockDim.x + threadIdx.x;
    if (t < TC3 * CDIM) {
        int n = t % TC3, k = t / TC3;
        float v = qkv_w[k * TC3 + n];
        if (n < CDIM) v *= scale;
        g_wqkv_h[n * CDIM + pk16(k)] = __float2half_rn(v);
    } else {
        int t2 = t - TC3 * CDIM;
        if (t2 < CDIM * CDIM) {
            int n = t2 % CDIM, k = t2 / CDIM;
            g_wproj_h[n * CDIM + pk16(k)] = __float2half_rn(proj_w[k * CDIM + n]);
        }
    }
}

__global__ void prepack_rm(const float* __restrict__ mask,
                           const float* __restrict__ bias_t, int nmask) {
    int t = blockIdx.x * blockDim.x + threadIdx.x;
    int total = nmask * NHEAD * 64 * 64;
    if (t >= total) return;
    int j = t & 63;
    int i = (t >> 6) & 63;
    int h = (t >> 12) & (NHEAD - 1);
    int v = t >> 14;
    float val = -1.0e30f;
    if (i < NTOK && j < NTOK) {
        int ri = i / 7, ci = i - ri * 7;
        int rj = j / 7, cj = j - rj * 7;
        int idx = (ri - rj + 6) * 13 + (ci - cj + 6);
        val = bias_t[idx * NHEAD + h] + mask[(size_t)v * NTOK * NTOK + i * NTOK + j];
    }
    g_rm[t] = val;
}

// ---------------- main persistent kernel -----------------------------------
__global__ __launch_bounds__(512, 1) void win_attn_kernel(
    const float* __restrict__ x,      const float* __restrict__ qkv_b,
    const float* __restrict__ proj_b, float* __restrict__ out,
    int nmask, int bw)
{
    extern __shared__ __half smh[];
    __half* WQ = smh + OFF_WQ;
    __half* WP = smh + OFF_WP;
    __half* Kb = smh + OFF_K;
    __half* VT = smh + OFF_VT;
    float*  BQ = (float*)(smh + OFF_BQ);
    float*  BP = BQ + TC3;

    __half* Xa = smh + OFF_X0;       // x / attn-out buffer (current window)
    __half* Qa = smh + OFF_X1;       // Q buffer (current window)

    const int tid  = threadIdx.x;
    const int warp = tid >> 5;
    const int lane = tid & 31;
    const int g    = lane >> 2;
    const int tig  = lane & 3;
    const int t4   = tig * 4;

    // G1 (warps 0-7): 32 rows x 96 cols;  G4 (warps 0-7): 32 rows x 32 cols
    const int r0G = (warp & 1) * 32;
    const int cbG1 = (warp >> 1) * 96;
    const int cbG4 = (warp >> 1) * 32;

    // ---------------- one-time init ----------------------------------------
    {
        const uint4* wq = (const uint4*)g_wqkv_h;
        for (int idx = tid; idx < 6144; idx += 512)
            *(uint4*)(WQ + (idx >> 4) * S + (idx & 15) * 8) = wq[idx];
        const uint4* wp = (const uint4*)g_wproj_h;
        for (int idx = tid; idx < 2048; idx += 512)
            *(uint4*)(WP + (idx >> 4) * S + (idx & 15) * 8) = wp[idx];
        uint4 z = {0, 0, 0, 0};
        for (int u = tid; u < 1280; u += 512)
            *(uint4*)(VT + u * 8) = z;
        const float scale = 0.17677669529663687f;
        if (tid < TC3) BQ[tid] = qkv_b[tid] * (tid < CDIM ? scale : 1.0f);
        if (tid < CDIM) BP[tid] = proj_b[tid];
        // stage first window's x into Xa
        int w0 = blockIdx.x;
        if (tid < NTOK * 8 && w0 < bw) {
            const float4* xr = (const float4*)(x + (size_t)w0 * NTOK * CDIM
                                               + (tid >> 3) * CDIM + (tid & 7) * 16);
            float4 f0 = xr[0], f1 = xr[1], f2 = xr[2], f3 = xr[3];
            uint4 lo, hi;
            lo.x = h2u(f0.x, f0.y);  lo.y = h2u(f2.x, f2.y);
            lo.z = h2u(f0.z, f0.w);  lo.w = h2u(f2.z, f2.w);
            hi.x = h2u(f1.x, f1.y);  hi.y = h2u(f3.x, f3.y);
            hi.z = h2u(f1.z, f1.w);  hi.w = h2u(f3.z, f3.w);
            uint4* d = (uint4*)(Xa + (tid >> 3) * S + (tid & 7) * 16);
            d[0] = lo; d[1] = hi;
        }
        for (int u = tid; u < 270; u += 512) {
            *(uint4*)(smh + OFF_X0 + NTOK * S + u * 8) = z;
            *(uint4*)(smh + OFF_X1 + NTOK * S + u * 8) = z;
        }
    }
    __syncthreads();

    const float L2E = 1.4426950408889634f;

    for (int w = blockIdx.x; w < bw; w += gridDim.x) {
        // ---------------- GEMM1 (warps 0-7): 32 rows x 96 cols --------------
        if (warp < 8) {
            float acc[2][12][4];
#pragma unroll
            for (int m = 0; m < 2; m++)
#pragma unroll
                for (int t = 0; t < 12; t++)
                    acc[m][t][0] = acc[m][t][1] = acc[m][t][2] = acc[m][t][3] = 0.f;
#pragma unroll
            for (int kk = 0; kk < 8; kk++) {
                const int kc = kk * 16;
                uint2 aA0 = *(uint2*)(Xa + (r0G + g)      * S + kc + t4);
                uint2 aB0 = *(uint2*)(Xa + (r0G + g + 8)  * S + kc + t4);
                uint2 aA1 = *(uint2*)(Xa + (r0G + g + 16) * S + kc + t4);
                uint2 aB1 = *(uint2*)(Xa + (r0G + g + 24) * S + kc + t4);
#pragma unroll
                for (int t = 0; t < 12; t++) {
                    uint2 b = *(uint2*)(WQ + (cbG1 + t * 8 + g) * S + kc + t4);
                    mma16(acc[0][t], aA0, aB0, b);
                    mma16(acc[1][t], aA1, aB1, b);
                }
            }
            // epilogue: 6 tile pairs per row-group, route by global n
#pragma unroll
            for (int m = 0; m < 2; m++) {
                const int rA = r0G + m * 16 + g, rB = rA + 8;
#pragma unroll
                for (int p = 0; p < 6; p++) {
                    const int gb  = cbG1 + p * 16;
                    const int gnE = gb + 2 * tig;
                    const int gnO = gb + 8 + 2 * tig;
                    const float* aE = acc[m][2 * p];
                    const float* aO = acc[m][2 * p + 1];
                    const float be0 = BQ[gnE], be1 = BQ[gnE + 1];
                    const float bo0 = BQ[gnO], bo1 = BQ[gnO + 1];
                    float vE00 = aE[0] + be0, vE01 = aE[1] + be1;
                    float vE10 = aE[2] + be0, vE11 = aE[3] + be1;
                    float vO00 = aO[0] + bo0, vO01 = aO[1] + bo1;
                    float vO10 = aO[2] + bo0, vO11 = aO[3] + bo1;
                    if (gb < 128) {
                        uint2 sA = { h2u(vE00, vE01), h2u(vO00, vO01) };
                        uint2 sB = { h2u(vE10, vE11), h2u(vO10, vO11) };
                        *(uint2*)(Qa + rA * S + gb + t4) = sA;
                        *(uint2*)(Qa + rB * S + gb + t4) = sB;
                    } else if (gb < 256) {
                        const int c = gb - 128;
                        uint2 sA = { h2u(vE00, vE01), h2u(vO00, vO01) };
                        uint2 sB = { h2u(vE10, vE11), h2u(vO10, vO11) };
                        *(uint2*)(Kb + rA * S + c + t4) = sA;
                        *(uint2*)(Kb + rB * S + c + t4) = sB;
                    } else {
                        const int cE = gb - 256 + 2 * tig;
                        const int cO = cE + 8;
                        if (rA < NTOK) {
                            const int pA = pk16(rA);
                            VT[cE * SVT + pA]       = __float2half_rn(vE00);
                            VT[(cE + 1) * SVT + pA] = __float2half_rn(vE01);
                            VT[cO * SVT + pA]       = __float2half_rn(vO00);
                            VT[(cO + 1) * SVT + pA] = __float2half_rn(vO01);
                        }
                        if (rB < NTOK) {
                            const int pB = pk16(rB);
                            VT[cE * SVT + pB]       = __float2half_rn(vE10);
                            VT[(cE + 1) * SVT + pB] = __float2half_rn(vE11);
                            VT[cO * SVT + pB]       = __float2half_rn(vO10);
                            VT[(cO + 1) * SVT + pB] = __float2half_rn(vO11);
                        }
                    }
                }
            }
        }
        __syncthreads();                                 // (B) Q/K/VT ready

        // ---------------- attention: all 16 warps = (head, m-tile) ----------
        {
            const int h   = warp >> 2;
            const int mt2 = warp & 3;
            const int rb2 = mt2 * 16;

            const int v = w % nmask;
            const float* rm0 = g_rm + ((size_t)((v * NHEAD + h) * 64 + rb2 + g)) * 64;
            const float* rm1 = rm0 + 8 * 64;
            float2 rv0[7], rv1[7];
#pragma unroll
            for (int t = 0; t < 7; t++) {
                const int j0 = t * 8 + 2 * tig;
                rv0[t] = *(const float2*)(rm0 + j0);
                rv1[t] = *(const float2*)(rm1 + j0);
            }

            float lv[7][4];
#pragma unroll
            for (int t = 0; t < 7; t++) lv[t][0] = lv[t][1] = lv[t][2] = lv[t][3] = 0.f;
#pragma unroll
            for (int kk = 0; kk < 2; kk++) {
                const int kc = h * 32 + kk * 16;
                uint2 aA = *(uint2*)(Qa + (rb2 + g)     * S + kc + t4);
                uint2 aB = *(uint2*)(Qa + (rb2 + g + 8) * S + kc + t4);
#pragma unroll
                for (int t = 0; t < 7; t++) {
                    uint2 b = *(uint2*)(Kb + (t * 8 + g) * S + kc + t4);
                    mma16(lv[t], aA, aB, b);
                }
            }
            float mx0 = -3.0e38f, mx1 = -3.0e38f;
#pragma unroll
            for (int t = 0; t < 7; t++) {
                lv[t][0] += rv0[t].x; lv[t][1] += rv0[t].y;
                lv[t][2] += rv1[t].x; lv[t][3] += rv1[t].y;
                mx0 = fmaxf(mx0, fmaxf(lv[t][0], lv[t][1]));
                mx1 = fmaxf(mx1, fmaxf(lv[t][2], lv[t][3]));
            }
            mx0 = fmaxf(mx0, __shfl_xor_sync(0xffffffffu, mx0, 1));
            mx0 = fmaxf(mx0, __shfl_xor_sync(0xffffffffu, mx0, 2));
            mx1 = fmaxf(mx1, __shfl_xor_sync(0xffffffffu, mx1, 1));
            mx1 = fmaxf(mx1, __shfl_xor_sync(0xffffffffu, mx1, 2));

            uint32_t e01[8], e23[8];
            e01[7] = 0u; e23[7] = 0u;
            float s0 = 0.f, s1 = 0.f;
#pragma unroll
            for (int t = 0; t < 7; t++) {
                e01[t] = ex2h2((lv[t][0] - mx0) * L2E, (lv[t][1] - mx0) * L2E);
                e23[t] = ex2h2((lv[t][2] - mx1) * L2E, (lv[t][3] - mx1) * L2E);
                float2 f0 = __half22float2(*(__half2*)&e01[t]);
                float2 f1 = __half22float2(*(__half2*)&e23[t]);
                s0 += f0.x + f0.y;
                s1 += f1.x + f1.y;
            }
            s0 += __shfl_xor_sync(0xffffffffu, s0, 1);
            s0 += __shfl_xor_sync(0xffffffffu, s0, 2);
            s1 += __shfl_xor_sync(0xffffffffu, s1, 1);
            s1 += __shfl_xor_sync(0xffffffffu, s1, 2);
            const float inv0 = 1.0f / s0, inv1 = 1.0f / s1;

            float a3[4][4];
#pragma unroll
            for (int t = 0; t < 4; t++) a3[t][0] = a3[t][1] = a3[t][2] = a3[t][3] = 0.f;
#pragma unroll
            for (int kk = 0; kk < 4; kk++) {
                uint2 alo = { e01[2 * kk], e01[2 * kk + 1] };
                uint2 ahi = { e23[2 * kk], e23[2 * kk + 1] };
#pragma unroll
                for (int t = 0; t < 4; t++) {
                    uint2 b = *(uint2*)(VT + (h * 32 + t * 8 + g) * SVT + kk * 16 + t4);
                    mma16(a3[t], alo, ahi, b);
                }
            }
#pragma unroll
            for (int p = 0; p < 2; p++) {
                const int gb = h * 32 + p * 16;
                uint2 sA = { h2u(a3[2 * p][0] * inv0,     a3[2 * p][1] * inv0),
                             h2u(a3[2 * p + 1][0] * inv0, a3[2 * p + 1][1] * inv0) };
                uint2 sB = { h2u(a3[2 * p][2] * inv1,     a3[2 * p][3] * inv1),
                             h2u(a3[2 * p + 1][2] * inv1, a3[2 * p + 1][3] * inv1) };
                *(uint2*)(Xa + (rb2 + g)     * S + gb + t4) = sA;
                *(uint2*)(Xa + (rb2 + g + 8) * S + gb + t4) = sB;
            }
        }
        __syncthreads();                                 // (C) ao ready, Q dead

        // ---------------- G4 (warps 0-7) / stage next x (warps 8-15) --------
        if (warp < 8) {
            float acc[2][4][4];
#pragma unroll
            for (int m = 0; m < 2; m++)
#pragma unroll
                for (int t = 0; t < 4; t++)
                    acc[m][t][0] = acc[m][t][1] = acc[m][t][2] = acc[m][t][3] = 0.f;
#pragma unroll
            for (int kk = 0; kk < 8; kk++) {
                const int kc = kk * 16;
                uint2 aA0 = *(uint2*)(Xa + (r0G + g)      * S + kc + t4);
                uint2 aB0 = *(uint2*)(Xa + (r0G + g + 8)  * S + kc + t4);
                uint2 aA1 = *(uint2*)(Xa + (r0G + g + 16) * S + kc + t4);
                uint2 aB1 = *(uint2*)(Xa + (r0G + g + 24) * S + kc + t4);
#pragma unroll
                for (int t = 0; t < 4; t++) {
                    uint2 b = *(uint2*)(WP + (cbG4 + t * 8 + g) * S + kc + t4);
                    mma16(acc[0][t], aA0, aB0, b);
                    mma16(acc[1][t], aA1, aB1, b);
                }
            }
            float* og = out + (size_t)w * NTOK * CDIM;
#pragma unroll
            for (int m = 0; m < 2; m++) {
                const int rA = r0G + m * 16 + g, rB = rA + 8;
#pragma unroll
                for (int t = 0; t < 4; t++) {
                    const int c0 = cbG4 + t * 8 + 2 * tig;
                    const float b0 = BP[c0], b1 = BP[c0 + 1];
                    if (rA < NTOK)
                        *(float2*)(og + rA * CDIM + c0) =
                            make_float2(acc[m][t][0] + b0, acc[m][t][1] + b1);
                    if (rB < NTOK)
                        *(float2*)(og + rB * CDIM + c0) =
                            make_float2(acc[m][t][2] + b0, acc[m][t][3] + b1);
                }
            }
        } else {
            // warps 8-15: load + stage next window's x into Qa (dead since C)
            const int wn = w + gridDim.x;
            if (wn < bw) {
                const float* xb = x + (size_t)wn * NTOK * CDIM;
                const int t0 = tid - 256;
                for (int q = t0; q < NTOK * 8; q += 256) {
                    const float4* xr = (const float4*)(xb + (q >> 3) * CDIM
                                                       + (q & 7) * 16);
                    float4 f0 = xr[0], f1 = xr[1], f2 = xr[2], f3 = xr[3];
                    uint4 lo, hi;
                    lo.x = h2u(f0.x, f0.y);  lo.y = h2u(f2.x, f2.y);
                    lo.z = h2u(f0.z, f0.w);  lo.w = h2u(f2.z, f2.w);
                    hi.x = h2u(f1.x, f1.y);  hi.y = h2u(f3.x, f3.y);
                    hi.z = h2u(f1.z, f1.w);  hi.w = h2u(f3.z, f3.w);
                    uint4* d = (uint4*)(Qa + (q >> 3) * S + (q & 7) * 16);
                    d[0] = lo; d[1] = hi;
                }
            }
        }
        __syncthreads();                                 // (D) G4 done, x staged

        __half* tmp = Xa; Xa = Qa; Qa = tmp;             // swap roles
    }
}

extern "C" void kernel_launch(void* const* d_in, const int* in_sizes, int n_in,
                              void* d_out, int out_size) {
    const float* x      = (const float*)d_in[0];
    const float* qkv_w  = (const float*)d_in[1];
    const float* qkv_b  = (const float*)d_in[2];
    const float* proj_w = (const float*)d_in[3];
    const float* proj_b = (const float*)d_in[4];
    const float* bias_t = (const float*)d_in[5];
    const float* mask   = (const float*)d_in[6];
    float* out = (float*)d_out;

    const int bw    = in_sizes[0] / (NTOK * CDIM);   // 4096
    const int nmask = in_sizes[6] / (NTOK * NTOK);   // 64

    prepack_w<<<(TC3 * CDIM + CDIM * CDIM + 255) / 256, 256>>>(qkv_w, proj_w);
    {
        int total = nmask * NHEAD * 64 * 64;
        prepack_rm<<<(total + 255) / 256, 256>>>(mask, bias_t, nmask);
    }

    int nsm = 0;
    cudaDeviceGetAttribute(&nsm, cudaDevAttrMultiProcessorCount, 0);
    if (nsm <= 0) nsm = 148;
    if (nsm > bw) nsm = bw;

    const size_t smem = SMEMH * sizeof(__half);      // 225280 B
    cudaFuncSetAttribute(win_attn_kernel,
                         cudaFuncAttributeMaxDynamicSharedMemorySize, (int)smem);
    win_attn_kernel<<<nsm, 512, smem>>>(x, qkv_b, proj_b, out, nmask, bw);
}

// round 17
// speedup vs baseline: 1.1954x; 1.1954x over previous
#include <cuda_runtime.h>
#include <cuda_fp16.h>
#include <cstdint>

// ---------------------------------------------------------------------------
// Swin WindowAttention, persistent FP16 mma.sync kernel (m16n8k16), round 17.
// R15 structure restored (best known: 16-warp 32x48 G1, 16-warp G4, register
// softmax via ex2.f16x2, ping-pong x staging, 3 barriers/window) + R16's
// scale folding into prepacked Q weights/bias. 512 threads, 1 CTA/SM.
// ---------------------------------------------------------------------------

namespace {
constexpr int NTOK  = 49;
constexpr int CDIM  = 128;
constexpr int NHEAD = 4;
constexpr int TC3   = 384;
constexpr int MAXW  = 64;
constexpr int S     = 144;   // fp16-unit stride (288 B), conflict-free
constexpr int SVT   = 80;    // VT stride

constexpr int OFF_WQ = 0;                    // [384][144] qkv_w resident
constexpr int OFF_WP = OFF_WQ + 384 * S;     // [128][144] proj_w resident
constexpr int OFF_X0 = OFF_WP + 128 * S;     // [64][144] ping buffer (x/ao or Q)
constexpr int OFF_X1 = OFF_X0 + 64 * S;      // [64][144] pong buffer
constexpr int OFF_K  = OFF_X1 + 64 * S;      // [64][144] K
constexpr int OFF_VT = OFF_K  + 64 * S;      // [128][80] V^T
constexpr int OFF_BQ = OFF_VT + 128 * SVT;   // 384 fp32 qkv_b + 128 fp32 proj_b
constexpr int SMEMH  = OFF_BQ + 1024;        // 112640 halfs = 225280 B
}

__device__ __half g_wqkv_h[TC3 * CDIM];            // [n=384][pk16(k=128)], Q pre-scaled
__device__ __half g_wproj_h[CDIM * CDIM];          // [n=128][pk16(k=128)]
__device__ float  g_rm[MAXW * NHEAD * 64 * 64];    // rpb+mask, padded -1e30

__device__ __forceinline__ int pk16(int k) {
    return (k & ~15) | (((k >> 1) & 3) << 2) | ((k & 8) >> 2) | (k & 1);
}

__device__ __forceinline__ uint32_t h2u(float a, float b) {
    __half2 h = __floats2half2_rn(a, b);
    return *reinterpret_cast<uint32_t*>(&h);
}

__device__ __forceinline__ void mma16(float* c, uint2 alo, uint2 ahi, uint2 b) {
    asm volatile(
        "mma.sync.aligned.m16n8k16.row.col.f32.f16.f16.f32 "
        "{%0,%1,%2,%3}, {%4,%5,%6,%7}, {%8,%9}, {%0,%1,%2,%3};"
        : "+f"(c[0]), "+f"(c[1]), "+f"(c[2]), "+f"(c[3])
        : "r"(alo.x), "r"(ahi.x), "r"(alo.y), "r"(ahi.y), "r"(b.x), "r"(b.y));
}

__device__ __forceinline__ uint32_t ex2h2(float a, float b) {
    __half2 h = __floats2half2_rn(a, b);
    uint32_t r;
    asm("ex2.approx.f16x2 %0, %1;" : "=r"(r) : "r"(*reinterpret_cast<uint32_t*>(&h)));
    return r;
}

// ---------------- prepack kernels ------------------------------------------
__global__ void prepack_w(const float* __restrict__ qkv_w,
                          const float* __restrict__ proj_w) {
    const float scale = 0.17677669529663687f;   // 32^-0.5, folded into Q cols
    int t = blockIdx.x * blockDim.x + threadIdx.x;
    if (t < TC3 * CDIM) {
        int n = t % TC3, k = t / TC3;
        float v = qkv_w[k * TC3 + n];
        if (n < CDIM) v *= scale;
        g_wqkv_h[n * CDIM + pk16(k)] = __float2half_rn(v);
    } else {
        int t2 = t - TC3 * CDIM;
        if (t2 < CDIM * CDIM) {
            int n = t2 % CDIM, k = t2 / CDIM;
            g_wproj_h[n * CDIM + pk16(k)] = __float2half_rn(proj_w[k * CDIM + n]);
        }
    }
}

__global__ void prepack_rm(const float* __restrict__ mask,
                           const float* __restrict__ bias_t, int nmask) {
    int t = blockIdx.x * blockDim.x + threadIdx.x;
    int total = nmask * NHEAD * 64 * 64;
    if (t >= total) return;
    int j = t & 63;
    int i = (t >> 6) & 63;
    int h = (t >> 12) & (NHEAD - 1);
    int v = t >> 14;
    float val = -1.0e30f;
    if (i < NTOK && j < NTOK) {
        int ri = i / 7, ci = i - ri * 7;
        int rj = j / 7, cj = j - rj * 7;
        int idx = (ri - rj + 6) * 13 + (ci - cj + 6);
        val = bias_t[idx * NHEAD + h] + mask[(size_t)v * NTOK * NTOK + i * NTOK + j];
    }
    g_rm[t] = val;
}

// ---------------- main persistent kernel -----------------------------------
__global__ __launch_bounds__(512, 1) void win_attn_kernel(
    const float* __restrict__ x,      const float* __restrict__ qkv_b,
    const float* __restrict__ proj_b, float* __restrict__ out,
    int nmask, int bw)
{
    extern __shared__ __half smh[];
    __half* WQ = smh + OFF_WQ;
    __half* WP = smh + OFF_WP;
    __half* Kb = smh + OFF_K;
    __half* VT = smh + OFF_VT;
    float*  BQ = (float*)(smh + OFF_BQ);
    float*  BP = BQ + TC3;

    __half* Xa = smh + OFF_X0;       // x / attn-out buffer (current window)
    __half* Qa = smh + OFF_X1;       // Q buffer (current window)

    const int tid  = threadIdx.x;
    const int warp = tid >> 5;
    const int lane = tid & 31;
    const int g    = lane >> 2;
    const int tig  = lane & 3;
    const int t4   = tig * 4;

    const int r0G1 = (warp & 1) * 32;     // G1: 32 rows x 48 cols, 16 warps
    const int cbG1 = (warp >> 1) * 48;
    const int mt = warp & 3;              // G4: 16 rows x 32 cols, 16 warps
    const int ng = warp >> 2;
    const int rb = mt * 16;

    const bool xthr = (tid < NTOK * 8);
    const int  xrow = tid >> 3, xcb = (tid & 7) * 16;

    // ---------------- one-time init ----------------------------------------
    {
        const uint4* wq = (const uint4*)g_wqkv_h;
        for (int idx = tid; idx < 6144; idx += 512)
            *(uint4*)(WQ + (idx >> 4) * S + (idx & 15) * 8) = wq[idx];
        const uint4* wp = (const uint4*)g_wproj_h;
        for (int idx = tid; idx < 2048; idx += 512)
            *(uint4*)(WP + (idx >> 4) * S + (idx & 15) * 8) = wp[idx];
        uint4 z = {0, 0, 0, 0};
        for (int u = tid; u < 1280; u += 512)
            *(uint4*)(VT + u * 8) = z;
        const float scale = 0.17677669529663687f;
        if (tid < TC3) BQ[tid] = qkv_b[tid] * (tid < CDIM ? scale : 1.0f);
        if (tid < CDIM) BP[tid] = proj_b[tid];
        // stage first window's x into Xa
        int w0 = blockIdx.x;
        if (xthr && w0 < bw) {
            const float4* xr = (const float4*)(x + (size_t)w0 * NTOK * CDIM
                                               + xrow * CDIM + xcb);
            float4 f0 = xr[0], f1 = xr[1], f2 = xr[2], f3 = xr[3];
            uint4 lo, hi;
            lo.x = h2u(f0.x, f0.y);  lo.y = h2u(f2.x, f2.y);
            lo.z = h2u(f0.z, f0.w);  lo.w = h2u(f2.z, f2.w);
            hi.x = h2u(f1.x, f1.y);  hi.y = h2u(f3.x, f3.y);
            hi.z = h2u(f1.z, f1.w);  hi.w = h2u(f3.z, f3.w);
            uint4* d = (uint4*)(Xa + xrow * S + xcb);
            d[0] = lo; d[1] = hi;
        }
        for (int u = tid; u < 270; u += 512) {
            *(uint4*)(smh + OFF_X0 + NTOK * S + u * 8) = z;
            *(uint4*)(smh + OFF_X1 + NTOK * S + u * 8) = z;
        }
    }
    __syncthreads();

    const float L2E = 1.4426950408889634f;

    for (int w = blockIdx.x; w < bw; w += gridDim.x) {
        // ---------------- GEMM1: warp = 32 rows x 48 cols (16 warps) --------
        {
            float acc[2][6][4];
#pragma unroll
            for (int m = 0; m < 2; m++)
#pragma unroll
                for (int t = 0; t < 6; t++)
                    acc[m][t][0] = acc[m][t][1] = acc[m][t][2] = acc[m][t][3] = 0.f;
#pragma unroll
            for (int kk = 0; kk < 8; kk++) {
                const int kc = kk * 16;
                uint2 aA0 = *(uint2*)(Xa + (r0G1 + g)      * S + kc + t4);
                uint2 aB0 = *(uint2*)(Xa + (r0G1 + g + 8)  * S + kc + t4);
                uint2 aA1 = *(uint2*)(Xa + (r0G1 + g + 16) * S + kc + t4);
                uint2 aB1 = *(uint2*)(Xa + (r0G1 + g + 24) * S + kc + t4);
#pragma unroll
                for (int t = 0; t < 6; t++) {
                    uint2 b = *(uint2*)(WQ + (cbG1 + t * 8 + g) * S + kc + t4);
                    mma16(acc[0][t], aA0, aB0, b);
                    mma16(acc[1][t], aA1, aB1, b);
                }
            }
#pragma unroll
            for (int m = 0; m < 2; m++) {
                const int rA = r0G1 + m * 16 + g, rB = rA + 8;
#pragma unroll
                for (int p = 0; p < 3; p++) {
                    const int gb  = cbG1 + p * 16;
                    const int gnE = gb + 2 * tig;
                    const int gnO = gb + 8 + 2 * tig;
                    const float* aE = acc[m][2 * p];
                    const float* aO = acc[m][2 * p + 1];
                    const float be0 = BQ[gnE], be1 = BQ[gnE + 1];
                    const float bo0 = BQ[gnO], bo1 = BQ[gnO + 1];
                    float vE00 = aE[0] + be0, vE01 = aE[1] + be1;
                    float vE10 = aE[2] + be0, vE11 = aE[3] + be1;
                    float vO00 = aO[0] + bo0, vO01 = aO[1] + bo1;
                    float vO10 = aO[2] + bo0, vO11 = aO[3] + bo1;
                    if (gb < 128) {      // Q (scale pre-folded into W/b)
                        uint2 sA = { h2u(vE00, vE01), h2u(vO00, vO01) };
                        uint2 sB = { h2u(vE10, vE11), h2u(vO10, vO11) };
                        *(uint2*)(Qa + rA * S + gb + t4) = sA;
                        *(uint2*)(Qa + rB * S + gb + t4) = sB;
                    } else if (gb < 256) {
                        const int c = gb - 128;
                        uint2 sA = { h2u(vE00, vE01), h2u(vO00, vO01) };
                        uint2 sB = { h2u(vE10, vE11), h2u(vO10, vO11) };
                        *(uint2*)(Kb + rA * S + c + t4) = sA;
                        *(uint2*)(Kb + rB * S + c + t4) = sB;
                    } else {
                        const int cE = gb - 256 + 2 * tig;
                        const int cO = cE + 8;
                        if (rA < NTOK) {
                            const int pA = pk16(rA);
                            VT[cE * SVT + pA]       = __float2half_rn(vE00);
                            VT[(cE + 1) * SVT + pA] = __float2half_rn(vE01);
                            VT[cO * SVT + pA]       = __float2half_rn(vO00);
                            VT[(cO + 1) * SVT + pA] = __float2half_rn(vO01);
                        }
                        if (rB < NTOK) {
                            const int pB = pk16(rB);
                            VT[cE * SVT + pB]       = __float2half_rn(vE10);
                            VT[(cE + 1) * SVT + pB] = __float2half_rn(vE11);
                            VT[cO * SVT + pB]       = __float2half_rn(vO10);
                            VT[(cO + 1) * SVT + pB] = __float2half_rn(vO11);
                        }
                    }
                }
            }
        }
        __syncthreads();                                 // (B) Q/K/VT ready

        // prefetch next window's x (hidden under attention + G4)
        float4 pfx0, pfx1, pfx2, pfx3;
        const int wn = w + gridDim.x;
        if (xthr && wn < bw) {
            const float4* xr = (const float4*)(x + (size_t)wn * NTOK * CDIM
                                               + xrow * CDIM + xcb);
            pfx0 = xr[0]; pfx1 = xr[1]; pfx2 = xr[2]; pfx3 = xr[3];
        }

        // ---------------- attention: warp = (head, m-tile), 16 warps --------
        {
            const int h   = warp >> 2;
            const int mt2 = warp & 3;
            const int rb2 = mt2 * 16;

            const int v = w % nmask;
            const float* rm0 = g_rm + ((size_t)((v * NHEAD + h) * 64 + rb2 + g)) * 64;
            const float* rm1 = rm0 + 8 * 64;
            float2 rv0[7], rv1[7];
#pragma unroll
            for (int t = 0; t < 7; t++) {
                const int j0 = t * 8 + 2 * tig;
                rv0[t] = *(const float2*)(rm0 + j0);
                rv1[t] = *(const float2*)(rm1 + j0);
            }

            float lv[7][4];
#pragma unroll
            for (int t = 0; t < 7; t++) lv[t][0] = lv[t][1] = lv[t][2] = lv[t][3] = 0.f;
#pragma unroll
            for (int kk = 0; kk < 2; kk++) {
                const int kc = h * 32 + kk * 16;
                uint2 aA = *(uint2*)(Qa + (rb2 + g)     * S + kc + t4);
                uint2 aB = *(uint2*)(Qa + (rb2 + g + 8) * S + kc + t4);
#pragma unroll
                for (int t = 0; t < 7; t++) {
                    uint2 b = *(uint2*)(Kb + (t * 8 + g) * S + kc + t4);
                    mma16(lv[t], aA, aB, b);
                }
            }
            float mx0 = -3.0e38f, mx1 = -3.0e38f;
#pragma unroll
            for (int t = 0; t < 7; t++) {
                lv[t][0] += rv0[t].x; lv[t][1] += rv0[t].y;
                lv[t][2] += rv1[t].x; lv[t][3] += rv1[t].y;
                mx0 = fmaxf(mx0, fmaxf(lv[t][0], lv[t][1]));
                mx1 = fmaxf(mx1, fmaxf(lv[t][2], lv[t][3]));
            }
            mx0 = fmaxf(mx0, __shfl_xor_sync(0xffffffffu, mx0, 1));
            mx0 = fmaxf(mx0, __shfl_xor_sync(0xffffffffu, mx0, 2));
            mx1 = fmaxf(mx1, __shfl_xor_sync(0xffffffffu, mx1, 1));
            mx1 = fmaxf(mx1, __shfl_xor_sync(0xffffffffu, mx1, 2));

            uint32_t e01[8], e23[8];
            e01[7] = 0u; e23[7] = 0u;
            float s0 = 0.f, s1 = 0.f;
#pragma unroll
            for (int t = 0; t < 7; t++) {
                e01[t] = ex2h2((lv[t][0] - mx0) * L2E, (lv[t][1] - mx0) * L2E);
                e23[t] = ex2h2((lv[t][2] - mx1) * L2E, (lv[t][3] - mx1) * L2E);
                float2 f0 = __half22float2(*(__half2*)&e01[t]);
                float2 f1 = __half22float2(*(__half2*)&e23[t]);
                s0 += f0.x + f0.y;
                s1 += f1.x + f1.y;
            }
            s0 += __shfl_xor_sync(0xffffffffu, s0, 1);
            s0 += __shfl_xor_sync(0xffffffffu, s0, 2);
            s1 += __shfl_xor_sync(0xffffffffu, s1, 1);
            s1 += __shfl_xor_sync(0xffffffffu, s1, 2);
            const float inv0 = 1.0f / s0, inv1 = 1.0f / s1;

            float a3[4][4];
#pragma unroll
            for (int t = 0; t < 4; t++) a3[t][0] = a3[t][1] = a3[t][2] = a3[t][3] = 0.f;
#pragma unroll
            for (int kk = 0; kk < 4; kk++) {
                uint2 alo = { e01[2 * kk], e01[2 * kk + 1] };
                uint2 ahi = { e23[2 * kk], e23[2 * kk + 1] };
#pragma unroll
                for (int t = 0; t < 4; t++) {
                    uint2 b = *(uint2*)(VT + (h * 32 + t * 8 + g) * SVT + kk * 16 + t4);
                    mma16(a3[t], alo, ahi, b);
                }
            }
#pragma unroll
            for (int p = 0; p < 2; p++) {
                const int gb = h * 32 + p * 16;
                uint2 sA = { h2u(a3[2 * p][0] * inv0,     a3[2 * p][1] * inv0),
                             h2u(a3[2 * p + 1][0] * inv0, a3[2 * p + 1][1] * inv0) };
                uint2 sB = { h2u(a3[2 * p][2] * inv1,     a3[2 * p][3] * inv1),
                             h2u(a3[2 * p + 1][2] * inv1, a3[2 * p + 1][3] * inv1) };
                *(uint2*)(Xa + (rb2 + g)     * S + gb + t4) = sA;
                *(uint2*)(Xa + (rb2 + g + 8) * S + gb + t4) = sB;
            }
        }
        __syncthreads();                                 // (C) ao ready, Q dead

        // ---------------- GEMM4 (16 warps) + stage next x into Qa ----------
        {
            float acc[4][4];
#pragma unroll
            for (int t = 0; t < 4; t++)
                acc[t][0] = acc[t][1] = acc[t][2] = acc[t][3] = 0.f;
#pragma unroll
            for (int kk = 0; kk < 8; kk++) {
                const int kc = kk * 16;
                uint2 aA = *(uint2*)(Xa + (rb + g)     * S + kc + t4);
                uint2 aB = *(uint2*)(Xa + (rb + g + 8) * S + kc + t4);
#pragma unroll
                for (int t = 0; t < 4; t++) {
                    uint2 b = *(uint2*)(WP + (ng * 32 + t * 8 + g) * S + kc + t4);
                    mma16(acc[t], aA, aB, b);
                }
            }
            float* og = out + (size_t)w * NTOK * CDIM;
            const int rA = rb + g, rB = rA + 8;
#pragma unroll
            for (int t = 0; t < 4; t++) {
                const int c0 = ng * 32 + t * 8 + 2 * tig;
                const float b0 = BP[c0], b1 = BP[c0 + 1];
                if (rA < NTOK)
                    *(float2*)(og + rA * CDIM + c0) =
                        make_float2(acc[t][0] + b0, acc[t][1] + b1);
                if (rB < NTOK)
                    *(float2*)(og + rB * CDIM + c0) =
                        make_float2(acc[t][2] + b0, acc[t][3] + b1);
            }
            // stage next window's x into Qa (free since bar C)
            if (xthr && wn < bw) {
                uint4 lo, hi;
                lo.x = h2u(pfx0.x, pfx0.y);  lo.y = h2u(pfx2.x, pfx2.y);
                lo.z = h2u(pfx0.z, pfx0.w);  lo.w = h2u(pfx2.z, pfx2.w);
                hi.x = h2u(pfx1.x, pfx1.y);  hi.y = h2u(pfx3.x, pfx3.y);
                hi.z = h2u(pfx1.z, pfx1.w);  hi.w = h2u(pfx3.z, pfx3.w);
                uint4* d = (uint4*)(Qa + xrow * S + xcb);
                d[0] = lo; d[1] = hi;
            }
        }
        __syncthreads();                                 // (D) G4 done, x staged

        __half* tmp = Xa; Xa = Qa; Qa = tmp;             // swap roles
    }
}

extern "C" void kernel_launch(void* const* d_in, const int* in_sizes, int n_in,
                              void* d_out, int out_size) {
    const float* x      = (const float*)d_in[0];
    const float* qkv_w  = (const float*)d_in[1];
    const float* qkv_b  = (const float*)d_in[2];
    const float* proj_w = (const float*)d_in[3];
    const float* proj_b = (const float*)d_in[4];
    const float* bias_t = (const float*)d_in[5];
    const float* mask   = (const float*)d_in[6];
    float* out = (float*)d_out;

    const int bw    = in_sizes[0] / (NTOK * CDIM);   // 4096
    const int nmask = in_sizes[6] / (NTOK * NTOK);   // 64

    prepack_w<<<(TC3 * CDIM + CDIM * CDIM + 255) / 256, 256>>>(qkv_w, proj_w);
    {
        int total = nmask * NHEAD * 64 * 64;
        prepack_rm<<<(total + 255) / 256, 256>>>(mask, bias_t, nmask);
    }

    int nsm = 0;
    cudaDeviceGetAttribute(&nsm, cudaDevAttrMultiProcessorCount, 0);
    if (nsm <= 0) nsm = 148;
    if (nsm > bw) nsm = bw;

    const size_t smem = SMEMH * sizeof(__half);      // 225280 B
    cudaFuncSetAttribute(win_attn_kernel,
                         cudaFuncAttributeMaxDynamicSharedMemorySize, (int)smem);
    win_attn_kernel<<<nsm, 512, smem>>>(x, qkv_b, proj_b, out, nmask, bw);
}